// round 12
// baseline (speedup 1.0000x reference)
#include <cuda_runtime.h>

// Inverse 2D Haar DWT, collapsed to the per-2x2-block butterfly:
//   out[2i  ,2j  ] = 0.5*(LL + LH + HL + HH)
//   out[2i  ,2j+1] = 0.5*(LL - LH + HL - HH)
//   out[2i+1,2j  ] = 0.5*(LL + LH - HL - HH)
//   out[2i+1,2j+1] = 0.5*(LL - LH - HL + HH)
//
// Shapes: in (32,128,56,56) f32 x4 -> out (32,128,112,112) f32
//
// FINAL kernel — every axis measured across 11 rounds:
//  - math collapsed to a per-2x2 butterfly (no conv, reflect-pad vanishes)
//  - one input column-pair per thread; float2 streaming loads, perfectly
//    linear across the grid (in_off = 2*idx)
//  - two float4 streaming stores per thread, contiguous across the warp
//    per output row (512B/warp/instruction, no split sectors)
//  - exact grid, no tail predicate; single %28 for index math
//  - 128-thread blocks: counter-optimal (ncu 56.80us, DRAM 79.7%, occ 85%).
//    256thr: 57.2-57.7us; 64thr: 60.0us (32-CTA/SM cap kills occupancy).
//  - one-shot blocks (persistent grid-stride: -7% DRAM, serialized MLP)
// Measured 6.32 TB/s HBM = this chip's mixed 4-read/1-write streaming
// ceiling; bytes are minimal (411MB); all compute pipes <12%.

#define W_OUT  112
#define WPAIRS 28

__global__ __launch_bounds__(128)
void idwt_haar_kernel(const float* __restrict__ LL,
                      const float* __restrict__ LH,
                      const float* __restrict__ HL,
                      const float* __restrict__ HH,
                      float* __restrict__ out)
{
    unsigned idx = blockIdx.x * blockDim.x + threadIdx.x;   // exact grid, no tail

    unsigned jj      = idx % WPAIRS;
    long     in_off  = 2L * idx;
    long     out_off = 8L * idx - 4L * jj;

    float2 ll = __ldcs(reinterpret_cast<const float2*>(LL + in_off));
    float2 lh = __ldcs(reinterpret_cast<const float2*>(LH + in_off));
    float2 hl = __ldcs(reinterpret_cast<const float2*>(HL + in_off));
    float2 hh = __ldcs(reinterpret_cast<const float2*>(HH + in_off));

    float p0 = ll.x + hl.x, m0 = ll.x - hl.x;
    float q0 = lh.x + hh.x, r0 = lh.x - hh.x;
    float p1 = ll.y + hl.y, m1 = ll.y - hl.y;
    float q1 = lh.y + hh.y, r1 = lh.y - hh.y;

    float4 row_even = make_float4(0.5f * (p0 + q0), 0.5f * (p0 - q0),
                                  0.5f * (p1 + q1), 0.5f * (p1 - q1));
    float4 row_odd  = make_float4(0.5f * (m0 + r0), 0.5f * (m0 - r0),
                                  0.5f * (m1 + r1), 0.5f * (m1 - r1));

    __stcs(reinterpret_cast<float4*>(out + out_off),         row_even);
    __stcs(reinterpret_cast<float4*>(out + out_off + W_OUT), row_odd);
}

extern "C" void kernel_launch(void* const* d_in, const int* in_sizes, int n_in,
                              void* d_out, int out_size)
{
    const float* LL = (const float*)d_in[0];
    const float* LH = (const float*)d_in[1];
    const float* HL = (const float*)d_in[2];
    const float* HH = (const float*)d_in[3];
    float* out = (float*)d_out;

    int total   = in_sizes[0] / 2;          // 6,422,528 = 50176 * 128 exactly
    int threads = 128;
    int blocks  = total / threads;          // exact division, no remainder

    idwt_haar_kernel<<<blocks, threads>>>(LL, LH, HL, HH, out);
}

// round 13
// speedup vs baseline: 1.0025x; 1.0025x over previous
#include <cuda_runtime.h>

// Inverse 2D Haar DWT, collapsed to the per-2x2-block butterfly:
//   out[2i  ,2j  ] = 0.5*(LL + LH + HL + HH)
//   out[2i  ,2j+1] = 0.5*(LL - LH + HL - HH)
//   out[2i+1,2j  ] = 0.5*(LL + LH - HL - HH)
//   out[2i+1,2j+1] = 0.5*(LL - LH - HL + HH)
//
// Shapes: in (32,128,56,56) f32 x4 -> out (32,128,112,112) f32
//
// FINAL kernel — 12 rounds, every axis bracketed with measurements:
//  - math collapsed to a per-2x2 butterfly (no conv; reflect-pad hits the
//    zero-inserted row/col and vanishes) -> bytes at the 411MB minimum
//  - one input column-pair per thread; float2 streaming loads, perfectly
//    linear across the grid (in_off = 2*idx)
//  - two float4 streaming stores per thread, contiguous across the warp
//    per output row (512B/warp/instruction, no split sectors)
//  - exact grid, no tail predicate; single %28 for all index math
//  - 128-thread one-shot blocks (best-or-tied counters, occ 85-88%;
//    64thr loses to the 32-CTA/SM cap, persistent loop loses 7% DRAM,
//    wider loads/stores neutral, float4-pair stores regress via sector
//    splits)
// Steady state: 6.25-6.32 TB/s HBM (79% of spec) = this chip's ceiling
// for a 4-read-stream/1-write-stream mix; all compute pipes <12%.

#define W_OUT  112
#define WPAIRS 28

__global__ __launch_bounds__(128)
void idwt_haar_kernel(const float* __restrict__ LL,
                      const float* __restrict__ LH,
                      const float* __restrict__ HL,
                      const float* __restrict__ HH,
                      float* __restrict__ out)
{
    unsigned idx = blockIdx.x * blockDim.x + threadIdx.x;   // exact grid, no tail

    unsigned jj      = idx % WPAIRS;
    long     in_off  = 2L * idx;
    long     out_off = 8L * idx - 4L * jj;

    float2 ll = __ldcs(reinterpret_cast<const float2*>(LL + in_off));
    float2 lh = __ldcs(reinterpret_cast<const float2*>(LH + in_off));
    float2 hl = __ldcs(reinterpret_cast<const float2*>(HL + in_off));
    float2 hh = __ldcs(reinterpret_cast<const float2*>(HH + in_off));

    float p0 = ll.x + hl.x, m0 = ll.x - hl.x;
    float q0 = lh.x + hh.x, r0 = lh.x - hh.x;
    float p1 = ll.y + hl.y, m1 = ll.y - hl.y;
    float q1 = lh.y + hh.y, r1 = lh.y - hh.y;

    float4 row_even = make_float4(0.5f * (p0 + q0), 0.5f * (p0 - q0),
                                  0.5f * (p1 + q1), 0.5f * (p1 - q1));
    float4 row_odd  = make_float4(0.5f * (m0 + r0), 0.5f * (m0 - r0),
                                  0.5f * (m1 + r1), 0.5f * (m1 - r1));

    __stcs(reinterpret_cast<float4*>(out + out_off),         row_even);
    __stcs(reinterpret_cast<float4*>(out + out_off + W_OUT), row_odd);
}

extern "C" void kernel_launch(void* const* d_in, const int* in_sizes, int n_in,
                              void* d_out, int out_size)
{
    const float* LL = (const float*)d_in[0];
    const float* LH = (const float*)d_in[1];
    const float* HL = (const float*)d_in[2];
    const float* HH = (const float*)d_in[3];
    float* out = (float*)d_out;

    int total   = in_sizes[0] / 2;          // 6,422,528 = 50176 * 128 exactly
    int threads = 128;
    int blocks  = total / threads;          // exact division, no remainder

    idwt_haar_kernel<<<blocks, threads>>>(LL, LH, HL, HH, out);
}

// round 14
// speedup vs baseline: 1.0035x; 1.0010x over previous
#include <cuda_runtime.h>

// Inverse 2D Haar DWT, collapsed to the per-2x2-block butterfly:
//   out[2i  ,2j  ] = 0.5*(LL + LH + HL + HH)
//   out[2i  ,2j+1] = 0.5*(LL - LH + HL - HH)
//   out[2i+1,2j  ] = 0.5*(LL + LH - HL - HH)
//   out[2i+1,2j+1] = 0.5*(LL - LH - HL + HH)
//
// Shapes: in (32,128,56,56) f32 x4 -> out (32,128,112,112) f32
//
// FINAL kernel — 13 rounds, all axes bracketed, noise floor quantified
// (same-binary repeats: ncu 56.8-58.2us, DRAM 77.7-79.7%, harness
// 63.7-64.0us):
//  - math collapsed to a per-2x2 butterfly (no conv; reflect-pad hits the
//    zero-inserted row/col and vanishes) -> bytes at the 411MB minimum
//  - one input column-pair per thread; float2 streaming loads, perfectly
//    linear across the grid (in_off = 2*idx)
//  - two float4 streaming stores per thread, contiguous across the warp
//    per output row (512B/warp/instruction, no split sectors)
//  - exact grid, no tail predicate; single %28 for all index math
//  - 128-thread one-shot blocks (best-or-tied counters, occ 85-88%;
//    64thr loses via the 32-CTA/SM cap, persistent loop loses 7% DRAM,
//    STG.256/float4-loads/vertical-batching all neutral-at-best)
// Steady state ~6.2-6.3 TB/s HBM = this chip's 4-read/1-write stream
// ceiling; all compute pipes <12%. Converged.

#define W_OUT  112
#define WPAIRS 28

__global__ __launch_bounds__(128)
void idwt_haar_kernel(const float* __restrict__ LL,
                      const float* __restrict__ LH,
                      const float* __restrict__ HL,
                      const float* __restrict__ HH,
                      float* __restrict__ out)
{
    unsigned idx = blockIdx.x * blockDim.x + threadIdx.x;   // exact grid, no tail

    unsigned jj      = idx % WPAIRS;
    long     in_off  = 2L * idx;
    long     out_off = 8L * idx - 4L * jj;

    float2 ll = __ldcs(reinterpret_cast<const float2*>(LL + in_off));
    float2 lh = __ldcs(reinterpret_cast<const float2*>(LH + in_off));
    float2 hl = __ldcs(reinterpret_cast<const float2*>(HL + in_off));
    float2 hh = __ldcs(reinterpret_cast<const float2*>(HH + in_off));

    float p0 = ll.x + hl.x, m0 = ll.x - hl.x;
    float q0 = lh.x + hh.x, r0 = lh.x - hh.x;
    float p1 = ll.y + hl.y, m1 = ll.y - hl.y;
    float q1 = lh.y + hh.y, r1 = lh.y - hh.y;

    float4 row_even = make_float4(0.5f * (p0 + q0), 0.5f * (p0 - q0),
                                  0.5f * (p1 + q1), 0.5f * (p1 - q1));
    float4 row_odd  = make_float4(0.5f * (m0 + r0), 0.5f * (m0 - r0),
                                  0.5f * (m1 + r1), 0.5f * (m1 - r1));

    __stcs(reinterpret_cast<float4*>(out + out_off),         row_even);
    __stcs(reinterpret_cast<float4*>(out + out_off + W_OUT), row_odd);
}

extern "C" void kernel_launch(void* const* d_in, const int* in_sizes, int n_in,
                              void* d_out, int out_size)
{
    const float* LL = (const float*)d_in[0];
    const float* LH = (const float*)d_in[1];
    const float* HL = (const float*)d_in[2];
    const float* HH = (const float*)d_in[3];
    float* out = (float*)d_out;

    int total   = in_sizes[0] / 2;          // 6,422,528 = 50176 * 128 exactly
    int threads = 128;
    int blocks  = total / threads;          // exact division, no remainder

    idwt_haar_kernel<<<blocks, threads>>>(LL, LH, HL, HH, out);
}